// round 2
// baseline (speedup 1.0000x reference)
#include <cuda_runtime.h>
#include <math.h>

#define N_TOT 2048
#define T_SEQ 70
#define HID   230
#define DIN   60
#define EMB_W 50
#define NBAG  64
#define BAGSZ 32
#define NREL  100

// ---------------- scratch (device globals; no allocation allowed) ----------
__device__ float g_emb[(size_t)T_SEQ * N_TOT * DIN];          // time-major [t][n][60]
__device__ float g_h[2 * 2 * N_TOT * HID];                    // [buf][dir][n][j] double-buffered
__device__ float g_tup[(size_t)2 * T_SEQ * N_TOT * HID];      // [dir][t][n][j]
__device__ float g_repre[N_TOT * HID];
__device__ float g_sen_s[NBAG * HID];
__device__ float g_loss_part[NBAG];

// ---------------- packed f32x2 helpers -------------------------------------
__device__ __forceinline__ unsigned long long packw(float w) {
    unsigned long long r;
    asm("mov.b64 %0, {%1, %1};" : "=l"(r) : "f"(w));
    return r;
}
__device__ __forceinline__ void fma2(float2 &a, const float2 &x, unsigned long long w2) {
    asm("fma.rn.f32x2 %0, %1, %2, %0;"
        : "+l"(reinterpret_cast<unsigned long long &>(a))
        : "l"(reinterpret_cast<const unsigned long long &>(x)), "l"(w2));
}

// ---------------- init ------------------------------------------------------
__global__ void zero_h_kernel() {
    int i = blockIdx.x * blockDim.x + threadIdx.x;
    if (i < 2 * 2 * N_TOT * HID) g_h[i] = 0.f;
}

// ---------------- embedding gather (time-major) ----------------------------
__global__ void gather_kernel(const int *__restrict__ sent, const int *__restrict__ p1,
                              const int *__restrict__ p2, const float *__restrict__ wemb,
                              const float *__restrict__ p1t, const float *__restrict__ p2t) {
    size_t idx = (size_t)blockIdx.x * blockDim.x + threadIdx.x;
    if (idx >= (size_t)N_TOT * T_SEQ * DIN) return;
    int k = (int)(idx % DIN);
    size_t nt = idx / DIN;
    int t = (int)(nt % T_SEQ);
    int n = (int)(nt / T_SEQ);
    float v;
    if (k < EMB_W) {
        v = wemb[(size_t)sent[n * T_SEQ + t] * EMB_W + k];
    } else if (k < EMB_W + 5) {
        v = p1t[p1[n * T_SEQ + t] * 5 + (k - EMB_W)];
    } else {
        v = p2t[p2[n * T_SEQ + t] * 5 + (k - EMB_W - 5)];
    }
    g_emb[((size_t)t * N_TOT + n) * DIN + k] = v;
}

// ---------------- GRU step: fused [emb|h] x [Wih|Whh]^T + gates -------------
// grid: (16 Mtiles, 8 jtiles, 2 dirs), block 256 (tx=tid&15 -> j, ty=tid>>4 -> samples)
// tile: 128 samples x 32 hidden-j. Per thread: 8 samples (4 packed pairs) x 2 j.
#define GRU_KPHASE(Wp, Xp, Kv, XSTR, AN)                                            \
    {                                                                                \
        const float *W_ = (Wp);                                                      \
        const float *X_ = (Xp);                                                      \
        const int K_ = (Kv);                                                         \
        const int XS_ = (XSTR);                                                      \
        for (int k0 = 0; k0 < K_; k0 += 16) {                                        \
            _Pragma("unroll") for (int it = 0; it < 8; it++) {                       \
                int l = tid + it * 256;                                              \
                int rr = l >> 4, kk = l & 15;                                        \
                int k = k0 + kk;                                                     \
                Xs[kk][rr] = (k < K_) ? X_[(size_t)(n0 + rr) * XS_ + k] : 0.f;       \
            }                                                                        \
            _Pragma("unroll") for (int it = 0; it < 6; it++) {                       \
                int l = tid + it * 256;                                              \
                int c = l >> 4, kk = l & 15;                                         \
                int gate = c >> 5;                                                   \
                int j = j0 + (c & 31);                                               \
                int k = k0 + kk;                                                     \
                float w = 0.f;                                                       \
                if (j < HID && k < K_) w = W_[(size_t)(gate * HID + j) * K_ + k];    \
                Ws[kk][c] = w;                                                       \
            }                                                                        \
            __syncthreads();                                                         \
            _Pragma("unroll") for (int kk = 0; kk < 16; kk++) {                      \
                float2 xv[4];                                                        \
                _Pragma("unroll") for (int i = 0; i < 4; i++)                        \
                    xv[i] = *(const float2 *)&Xs[kk][ty * 2 + i * 32];               \
                _Pragma("unroll") for (int jj = 0; jj < 2; jj++) {                   \
                    int c = tx * 2 + jj;                                             \
                    unsigned long long wr2 = packw(Ws[kk][c]);                       \
                    unsigned long long wz2 = packw(Ws[kk][32 + c]);                  \
                    unsigned long long wn2 = packw(Ws[kk][64 + c]);                  \
                    _Pragma("unroll") for (int i = 0; i < 4; i++) {                  \
                        fma2(ar[i][jj], xv[i], wr2);                                 \
                        fma2(az[i][jj], xv[i], wz2);                                 \
                        fma2(AN[i][jj], xv[i], wn2);                                 \
                    }                                                                \
                }                                                                    \
            }                                                                        \
            __syncthreads();                                                         \
        }                                                                            \
    }

__global__ void __launch_bounds__(256, 2) gru_step_kernel(
    int s,
    const float *__restrict__ Wihf, const float *__restrict__ Whhf,
    const float *__restrict__ bihf, const float *__restrict__ bhhf,
    const float *__restrict__ Wihb, const float *__restrict__ Whhb,
    const float *__restrict__ bihb, const float *__restrict__ bhhb) {
    const int dir = blockIdx.z;
    const int t = (dir == 0) ? s : (T_SEQ - 1 - s);
    const float *Wih = dir ? Wihb : Wihf;
    const float *Whh = dir ? Whhb : Whhf;
    const float *bih = dir ? bihb : bihf;
    const float *bhh = dir ? bhhb : bhhf;

    const int n0 = blockIdx.x * 128;
    const int j0 = blockIdx.y * 32;
    const int tid = threadIdx.x;
    const int tx = tid & 15;
    const int ty = tid >> 4;

    const float *hin = g_h + (size_t)((s & 1) * 2 + dir) * N_TOT * HID;
    float *hout = g_h + (size_t)(((s + 1) & 1) * 2 + dir) * N_TOT * HID;

    __shared__ float Xs[16][130];
    __shared__ float Ws[16][97];

    float2 ar[4][2], az[4][2], an1[4][2], an2[4][2];
#pragma unroll
    for (int i = 0; i < 4; i++)
#pragma unroll
        for (int jj = 0; jj < 2; jj++) {
            ar[i][jj] = make_float2(0.f, 0.f);
            az[i][jj] = make_float2(0.f, 0.f);
            an1[i][jj] = make_float2(0.f, 0.f);
            an2[i][jj] = make_float2(0.f, 0.f);
        }

    // phase 1: x = emb_t  (K=60)   accumulates r, z, i_n
    GRU_KPHASE(Wih, g_emb + (size_t)t * N_TOT * DIN, DIN, DIN, an1);
    // phase 2: x = h_prev (K=230)  accumulates r, z, h_n
    GRU_KPHASE(Whh, hin, HID, HID, an2);

    // epilogue: gates + state update
#pragma unroll
    for (int jj = 0; jj < 2; jj++) {
        int j = j0 + tx * 2 + jj;
        if (j >= HID) continue;
        float br = bih[j] + bhh[j];
        float bz = bih[HID + j] + bhh[HID + j];
        float bi_n = bih[2 * HID + j];
        float bh_n = bhh[2 * HID + j];
#pragma unroll
        for (int i = 0; i < 4; i++) {
            int nb = n0 + ty * 2 + i * 32;
            float arv[2] = {ar[i][jj].x, ar[i][jj].y};
            float azv[2] = {az[i][jj].x, az[i][jj].y};
            float a1v[2] = {an1[i][jj].x, an1[i][jj].y};
            float a2v[2] = {an2[i][jj].x, an2[i][jj].y};
#pragma unroll
            for (int p = 0; p < 2; p++) {
                int n = nb + p;
                float r = 1.f / (1.f + expf(-(arv[p] + br)));
                float z = 1.f / (1.f + expf(-(azv[p] + bz)));
                float nn = tanhf(a1v[p] + bi_n + r * (a2v[p] + bh_n));
                float hold = hin[(size_t)n * HID + j];
                float hnew = (1.f - z) * nn + z * hold;
                hout[(size_t)n * HID + j] = hnew;
                g_tup[(((size_t)dir * T_SEQ + t) * N_TOT + n) * HID + j] = hnew;
            }
        }
    }
}

// ---------------- word-level attention (online softmax, single pass) -------
__global__ void __launch_bounds__(256) attn_kernel(const float *__restrict__ att_w) {
    const int n = blockIdx.x;
    const int tid = threadIdx.x;
    __shared__ float xsum[HID];
    __shared__ float red[8];
    __shared__ float s_bc;

    float acc = 0.f;
    float m = -1e30f, denom = 0.f;
    float w = (tid < HID) ? att_w[tid] : 0.f;

    for (int t = 0; t < T_SEQ; t++) {
        if (tid < HID) {
            size_t i0 = (((size_t)0 * T_SEQ + t) * N_TOT + n) * HID + tid;
            size_t i1 = (((size_t)1 * T_SEQ + t) * N_TOT + n) * HID + tid;
            xsum[tid] = g_tup[i0] + g_tup[i1];
        }
        __syncthreads();
        float part = (tid < HID) ? tanhf(xsum[tid]) * w : 0.f;
#pragma unroll
        for (int o = 16; o > 0; o >>= 1) part += __shfl_down_sync(0xffffffffu, part, o);
        if ((tid & 31) == 0) red[tid >> 5] = part;
        __syncthreads();
        if (tid == 0) {
            float sm = 0.f;
#pragma unroll
            for (int q = 0; q < 8; q++) sm += red[q];
            s_bc = sm;
        }
        __syncthreads();
        float st = s_bc;
        float mn = fmaxf(m, st);
        float c = expf(m - mn);
        float e = expf(st - mn);
        denom = denom * c + e;
        if (tid < HID) acc = acc * c + e * xsum[tid];
        m = mn;
        __syncthreads();
    }
    if (tid < HID) g_repre[n * HID + tid] = tanhf(acc / denom);
}

// ---------------- bag (sentence-level) attention ----------------------------
__global__ void __launch_bounds__(256) bag_kernel(const float *__restrict__ sen_a,
                                                  const float *__restrict__ sen_r) {
    const int b = blockIdx.x;
    const int tid = threadIdx.x;
    __shared__ float R[BAGSZ][HID];
    __shared__ float sv[BAGSZ];
    __shared__ float alpha[BAGSZ];

    for (int l = tid; l < BAGSZ * HID; l += 256) {
        int i = l / HID, j = l % HID;
        R[i][j] = g_repre[(b * BAGSZ + i) * HID + j];
    }
    __syncthreads();
    int wid = tid >> 5, lane = tid & 31;
    for (int i = wid; i < BAGSZ; i += 8) {
        float p = 0.f;
        for (int j = lane; j < HID; j += 32) p += R[i][j] * sen_a[j] * sen_r[j];
#pragma unroll
        for (int o = 16; o > 0; o >>= 1) p += __shfl_down_sync(0xffffffffu, p, o);
        if (lane == 0) sv[i] = p;
    }
    __syncthreads();
    if (tid == 0) {
        float mm = -1e30f;
        for (int i = 0; i < BAGSZ; i++) mm = fmaxf(mm, sv[i]);
        float ss = 0.f;
        for (int i = 0; i < BAGSZ; i++) {
            float e = expf(sv[i] - mm);
            alpha[i] = e;
            ss += e;
        }
        for (int i = 0; i < BAGSZ; i++) alpha[i] /= ss;
    }
    __syncthreads();
    for (int j = tid; j < HID; j += 256) {
        float a = 0.f;
#pragma unroll 4
        for (int i = 0; i < BAGSZ; i++) a += alpha[i] * R[i][j];
        g_sen_s[b * HID + j] = a;
    }
}

// ---------------- logits / prob / bce / acc ---------------------------------
__global__ void __launch_bounds__(128) logits_kernel(const float *__restrict__ rel,
                                                     const float *__restrict__ sen_d,
                                                     const float *__restrict__ y,
                                                     float *__restrict__ out) {
    const int b = blockIdx.x;
    const int tid = threadIdx.x;
    __shared__ float ss[HID];
    __shared__ float lg[NREL];
    __shared__ float mmax;
    __shared__ int amax;
    __shared__ float dsum;

    for (int j = tid; j < HID; j += 128) ss[j] = g_sen_s[b * HID + j];
    __syncthreads();
    if (tid < NREL) {
        float a = sen_d[tid];
        const float *row = rel + (size_t)tid * HID;
        for (int j = 0; j < HID; j++) a += ss[j] * row[j];
        lg[tid] = a;
    }
    __syncthreads();
    if (tid == 0) {
        float mm = lg[0];
        int am = 0;
        for (int c = 1; c < NREL; c++)
            if (lg[c] > mm) { mm = lg[c]; am = c; }
        mmax = mm;
        amax = am;
        float sum = 0.f;
        for (int c = 0; c < NREL; c++) sum += expf(lg[c] - mm);
        dsum = sum;
    }
    __syncthreads();
    if (tid < NREL) {
        out[1 + NBAG + b * NREL + tid] = expf(lg[tid] - mmax) / dsum;
    }
    if (tid == 0) {
        float loss = 0.f;
        int lab = 0;
        for (int c = 0; c < NREL; c++) {
            float l = lg[c];
            float yv = y[b * NREL + c];
            loss += fmaxf(l, 0.f) - l * yv + log1pf(expf(-fabsf(l)));
            if (yv > 0.5f) lab = c;
        }
        g_loss_part[b] = loss / (float)NREL;
        out[1 + b] = (amax == lab) ? 1.f : 0.f;
    }
}

__global__ void loss_sum_kernel(float *__restrict__ out) {
    if (threadIdx.x == 0) {
        float s = 0.f;
        for (int b = 0; b < NBAG; b++) s += g_loss_part[b];
        out[0] = s;
    }
}

// ---------------- launch -----------------------------------------------------
extern "C" void kernel_launch(void *const *d_in, const int *in_sizes, int n_in,
                              void *d_out, int out_size) {
    const int *sentence = (const int *)d_in[0];
    const int *pos1 = (const int *)d_in[1];
    const int *pos2 = (const int *)d_in[2];
    /* d_in[3] total_shape: bags are fixed size 32 (arange(65)*32) */
    const float *y_batch = (const float *)d_in[4];
    const float *word_emb = (const float *)d_in[5];
    const float *p1t = (const float *)d_in[6];
    const float *p2t = (const float *)d_in[7];
    const float *Wihf = (const float *)d_in[8];
    const float *Whhf = (const float *)d_in[9];
    const float *bihf = (const float *)d_in[10];
    const float *bhhf = (const float *)d_in[11];
    const float *Wihb = (const float *)d_in[12];
    const float *Whhb = (const float *)d_in[13];
    const float *bihb = (const float *)d_in[14];
    const float *bhhb = (const float *)d_in[15];
    const float *attw = (const float *)d_in[16];
    const float *sena = (const float *)d_in[17];
    const float *senr = (const float *)d_in[18];
    const float *rel = (const float *)d_in[19];
    const float *send = (const float *)d_in[20];
    float *out = (float *)d_out;

    zero_h_kernel<<<(2 * 2 * N_TOT * HID + 255) / 256, 256>>>();
    gather_kernel<<<(int)(((size_t)N_TOT * T_SEQ * DIN + 255) / 256), 256>>>(
        sentence, pos1, pos2, word_emb, p1t, p2t);

    dim3 grid(16, 8, 2);
    for (int s = 0; s < T_SEQ; s++) {
        gru_step_kernel<<<grid, 256>>>(s, Wihf, Whhf, bihf, bhhf, Wihb, Whhb, bihb, bhhb);
    }

    attn_kernel<<<N_TOT, 256>>>(attw);
    bag_kernel<<<NBAG, 256>>>(sena, senr);
    logits_kernel<<<NBAG, 128>>>(rel, send, y_batch, out);
    loss_sum_kernel<<<1, 32>>>(out);
}

// round 4
// speedup vs baseline: 1.3667x; 1.3667x over previous
#include <cuda_runtime.h>
#include <cuda_bf16.h>
#include <math.h>
#include <stdint.h>

#define N_TOT 2048
#define T_SEQ 70
#define HID   230
#define DIN   60
#define EMB_W 50
#define NBAG  64
#define BAGSZ 32
#define NREL  100

// GRU step tiling: M=128, N=128 (32 j x 4 gates), K=320 in 10 chunks of 32.
// smem per stage: 4 arrays (A_hi, A_lo, B_hi, B_lo) of [128][40] bf16 = 40960 B.
#define CH_PAD   40
#define ARR_B    (128 * CH_PAD * 2)       // 10240
#define STAGE_B  (4 * ARR_B)              // 40960
#define OLD_OFF  (2 * STAGE_B)            // 81920
#define SMEM_DYN (OLD_OFF + 32 * 128 * 4) // 98304

// ---------------- device scratch ----------------
__device__ __align__(128) __nv_bfloat16 g_Wt[(size_t)2 * 8 * 2 * 10 * 128 * 32]; // [dir][jt][part][chunk][128][32]
__device__ __align__(128) __nv_bfloat16 g_embsp[(size_t)T_SEQ * 2 * N_TOT * 64]; // [t][part][n][64]
__device__ __align__(128) __nv_bfloat16 g_hbf[(size_t)2 * 2 * 2 * N_TOT * 256];  // [buf][dir][part][n][256]
__device__ float g_hT[(size_t)2 * 2 * 256 * N_TOT];                               // [buf][dir][j][n]
__device__ float g_tup[(size_t)2 * T_SEQ * N_TOT * HID];                          // [dir][t][n][j]
__device__ float g_repre[N_TOT * HID];
__device__ float g_sen_s[NBAG * HID];
__device__ float g_loss_part[NBAG];

// ---------------- ptx helpers ----------------
__device__ __forceinline__ uint32_t smem_u32(const void *p) {
    uint32_t a;
    asm("{ .reg .u64 t; cvta.to.shared.u64 t, %1; cvt.u32.u64 %0, t; }" : "=r"(a) : "l"(p));
    return a;
}
__device__ __forceinline__ void cpa16(uint32_t dst, const void *src) {
    asm volatile("cp.async.ca.shared.global [%0], [%1], 16;" :: "r"(dst), "l"(src));
}
#define CP_COMMIT() asm volatile("cp.async.commit_group;" ::: "memory")
#define CP_WAIT1()  asm volatile("cp.async.wait_group 1;" ::: "memory")
#define CP_WAIT0()  asm volatile("cp.async.wait_group 0;" ::: "memory")
#define LDSM4(r, a)                                                                   \
    asm volatile("ldmatrix.sync.aligned.m8n8.x4.shared.b16 {%0,%1,%2,%3}, [%4];"      \
                 : "=r"((r)[0]), "=r"((r)[1]), "=r"((r)[2]), "=r"((r)[3]) : "r"(a))
#define MMA16816(c, a, b0, b1)                                                        \
    asm volatile("mma.sync.aligned.m16n8k16.row.col.f32.bf16.bf16.f32 "               \
                 "{%0,%1,%2,%3},{%4,%5,%6,%7},{%8,%9},{%0,%1,%2,%3};"                 \
                 : "+f"((c)[0]), "+f"((c)[1]), "+f"((c)[2]), "+f"((c)[3])             \
                 : "r"((a)[0]), "r"((a)[1]), "r"((a)[2]), "r"((a)[3]), "r"(b0), "r"(b1))

__device__ __forceinline__ uint32_t pack2(__nv_bfloat16 a, __nv_bfloat16 b) {
    unsigned short ra = *(unsigned short *)&a, rb = *(unsigned short *)&b;
    return (uint32_t)ra | ((uint32_t)rb << 16);
}

// ---------------- prep kernels ----------------
__global__ void zero_kernel() {
    size_t i = (size_t)blockIdx.x * blockDim.x + threadIdx.x;
    size_t nh = (size_t)2 * 2 * 2 * N_TOT * 256 / 2;
    if (i < nh) ((uint32_t *)g_hbf)[i] = 0u;
    if (i < (size_t)2 * 2 * 256 * N_TOT) g_hT[i] = 0.f;
}

// weights -> [dir][jt][part(hi/lo)][chunk][row 128][k 32], rows = j_local*4+gate
__global__ void prep_w_kernel(const float *__restrict__ Wihf, const float *__restrict__ Whhf,
                              const float *__restrict__ Wihb, const float *__restrict__ Whhb) {
    int idx = blockIdx.x * blockDim.x + threadIdx.x;
    if (idx >= 2 * 8 * 10 * 128 * 32) return;
    int kc = idx & 31;
    int r = (idx >> 5) & 127;
    int rest = idx >> 12;            // 0..159
    int c = rest % 10;
    int jt = (rest / 10) & 7;
    int dir = rest / 80;
    const float *Wih = dir ? Wihb : Wihf;
    const float *Whh = dir ? Whhb : Whhf;
    int j = jt * 32 + (r >> 2);
    int g = r & 3;
    float v = 0.f;
    if (j < HID) {
        if (c < 2) {                 // emb chunks: k = c*32+kc, gates 0..2 from Wih
            int k = c * 32 + kc;
            if (k < DIN && g < 3) v = Wih[(g * HID + j) * DIN + k];
        } else {                     // h chunks: kh = (c-2)*32+kc, gates 0,1,3 from Whh
            int kh = (c - 2) * 32 + kc;
            if (kh < HID) {
                if (g < 2) v = Whh[(g * HID + j) * HID + kh];
                else if (g == 3) v = Whh[(2 * HID + j) * HID + kh];
            }
        }
    }
    __nv_bfloat16 hi = __float2bfloat16(v);
    __nv_bfloat16 lo = __float2bfloat16(v - __bfloat162float(hi));
    size_t i0 = ((((size_t)(dir * 8 + jt) * 2 + 0) * 10 + c) * 128 + r) * 32 + kc;
    size_t i1 = ((((size_t)(dir * 8 + jt) * 2 + 1) * 10 + c) * 128 + r) * 32 + kc;
    g_Wt[i0] = hi;
    g_Wt[i1] = lo;
}

__global__ void gather_kernel(const int *__restrict__ sent, const int *__restrict__ p1,
                              const int *__restrict__ p2, const float *__restrict__ wemb,
                              const float *__restrict__ p1t, const float *__restrict__ p2t) {
    size_t idx = (size_t)blockIdx.x * blockDim.x + threadIdx.x;
    if (idx >= (size_t)N_TOT * T_SEQ * 64) return;
    int k = (int)(idx & 63);
    size_t nt = idx >> 6;
    int t = (int)(nt % T_SEQ);
    int n = (int)(nt / T_SEQ);
    float v = 0.f;
    if (k < EMB_W) v = wemb[(size_t)sent[n * T_SEQ + t] * EMB_W + k];
    else if (k < EMB_W + 5) v = p1t[p1[n * T_SEQ + t] * 5 + (k - EMB_W)];
    else if (k < DIN) v = p2t[p2[n * T_SEQ + t] * 5 + (k - EMB_W - 5)];
    __nv_bfloat16 hi = __float2bfloat16(v);
    __nv_bfloat16 lo = __float2bfloat16(v - __bfloat162float(hi));
    g_embsp[((size_t)(t * 2 + 0) * N_TOT + n) * 64 + k] = hi;
    g_embsp[((size_t)(t * 2 + 1) * N_TOT + n) * 64 + k] = lo;
}

// ---------------- GRU step (mma.sync bf16, 3-pass split) ----------------
__global__ void __launch_bounds__(256, 2) gru_step_kernel(
    int s,
    const float *__restrict__ bihf, const float *__restrict__ bhhf,
    const float *__restrict__ bihb, const float *__restrict__ bhhb) {
    extern __shared__ char dsm[];
    const int dir = blockIdx.z;
    const int t = dir ? (T_SEQ - 1 - s) : s;
    const int n0 = blockIdx.x * 128;
    const int jt = blockIdx.y;
    const int tid = threadIdx.x;
    const int lane = tid & 31, wid = tid >> 5;
    const int warpM = wid & 3, warpN = wid >> 2;
    const int bufi = s & 1, bufo = (s + 1) & 1;
    const float *bih = dir ? bihb : bihf;
    const float *bhh = dir ? bhhb : bhhf;

    const uint32_t base = smem_u32(dsm);
    __shared__ float bs[4][32];
    if (tid < 32) {
        int j = jt * 32 + tid;
        bool ok = j < HID;
        bs[0][tid] = ok ? (bih[j] + bhh[j]) : 0.f;
        bs[1][tid] = ok ? (bih[HID + j] + bhh[HID + j]) : 0.f;
        bs[2][tid] = ok ? bih[2 * HID + j] : 0.f;
        bs[3][tid] = ok ? bhh[2 * HID + j] : 0.f;
    }

    const __nv_bfloat16 *embp = g_embsp + (size_t)t * 2 * N_TOT * 64 + (size_t)n0 * 64;
    const __nv_bfloat16 *hbfp = g_hbf + (size_t)((bufi * 2 + dir) * 2) * N_TOT * 256 + (size_t)n0 * 256;
    const __nv_bfloat16 *wbase = g_Wt + (size_t)(dir * 8 + jt) * 2 * 10 * 4096;

    // issue chunk c into stage c&1
    auto issue = [&](int c) {
        uint32_t stB = base + (c & 1) * STAGE_B;
#pragma unroll
        for (int part = 0; part < 2; part++) {
            const __nv_bfloat16 *Ap;
            int strideA;
            if (c < 2) { Ap = embp + (size_t)part * N_TOT * 64 + c * 32; strideA = 64; }
            else { Ap = hbfp + (size_t)part * N_TOT * 256 + (c - 2) * 32; strideA = 256; }
            const __nv_bfloat16 *Bp = wbase + (size_t)(part * 10 + c) * 4096;
#pragma unroll
            for (int it = 0; it < 2; it++) {
                int l = it * 256 + tid;
                int row = l >> 2, seg = l & 3;
                cpa16(stB + part * ARR_B + row * (CH_PAD * 2) + seg * 16,
                      Ap + (size_t)row * strideA + seg * 8);
                cpa16(stB + 2 * ARR_B + part * ARR_B + row * (CH_PAD * 2) + seg * 16,
                      Bp + row * 32 + seg * 8);
            }
        }
        CP_COMMIT();
    };

    issue(0);
    issue(1);

    // preload previous h (fp32, [j][n] coalesced) into OLD
    {
        float *OLD = (float *)(dsm + OLD_OFF);
        const float *hTold = g_hT + ((size_t)(bufi * 2 + dir) * 256 + jt * 32) * N_TOT + n0;
#pragma unroll
        for (int it = 0; it < 16; it++) {
            int idx = tid + it * 256;
            int jl = idx >> 7, nl = idx & 127;
            OLD[jl * 128 + nl] = hTold[(size_t)jl * N_TOT + nl];
        }
    }

    float acc[16][4];
#pragma unroll
    for (int i = 0; i < 16; i++)
#pragma unroll
        for (int q = 0; q < 4; q++) acc[i][q] = 0.f;

    const int laneR = lane & 15;
    const int laneC = (lane >> 4) * 16;

    for (int c = 0; c < 10; c++) {
        if (c < 9) CP_WAIT1(); else CP_WAIT0();
        __syncthreads();
        uint32_t sA = base + (c & 1) * STAGE_B;
        uint32_t sB = sA + 2 * ARR_B;
#pragma unroll
        for (int ks = 0; ks < 2; ks++) {
            uint32_t ah[2][4], al[2][4];
#pragma unroll
            for (int mi = 0; mi < 2; mi++) {
                uint32_t ra = (uint32_t)(warpM * 32 + mi * 16 + laneR) * (CH_PAD * 2) + laneC + ks * 32;
                LDSM4(ah[mi], sA + ra);
                LDSM4(al[mi], sA + ARR_B + ra);
            }
#pragma unroll
            for (int np = 0; np < 4; np++) {
                uint32_t rb = (uint32_t)(warpN * 64 + np * 16 + laneR) * (CH_PAD * 2) + laneC + ks * 32;
                uint32_t bh[4], bl[4];
                LDSM4(bh, sB + rb);
                LDSM4(bl, sB + ARR_B + rb);
#pragma unroll
                for (int mi = 0; mi < 2; mi++) {
                    float *c0 = acc[mi * 8 + np * 2];
                    float *c1 = acc[mi * 8 + np * 2 + 1];
                    MMA16816(c0, ah[mi], bh[0], bh[2]);
                    MMA16816(c0, ah[mi], bl[0], bl[2]);
                    MMA16816(c0, al[mi], bh[0], bh[2]);
                    MMA16816(c1, ah[mi], bh[1], bh[3]);
                    MMA16816(c1, ah[mi], bl[1], bl[3]);
                    MMA16816(c1, al[mi], bh[1], bh[3]);
                }
            }
        }
        __syncthreads();
        if (c + 2 < 10) issue(c + 2);
    }

    // ---- epilogue: gates ----
    float *stF = (float *)dsm;                   // [32][132] (overlaps stage0, now idle)
    float *OLD = (float *)(dsm + OLD_OFF);
    const int gr = lane >> 2, lc = lane & 3;
#pragma unroll
    for (int mi = 0; mi < 2; mi++)
#pragma unroll
        for (int ni = 0; ni < 8; ni++) {
            float *cc = acc[mi * 8 + ni];
            float p0 = __shfl_xor_sync(0xffffffffu, cc[0], 1);
            float p1 = __shfl_xor_sync(0xffffffffu, cc[1], 1);
            float p2 = __shfl_xor_sync(0xffffffffu, cc[2], 1);
            float p3 = __shfl_xor_sync(0xffffffffu, cc[3], 1);
            if ((lc & 1) == 0) {
                int jl = warpN * 16 + ni * 2 + (lc >> 1);
                int j = jt * 32 + jl;
                int m0 = warpM * 32 + mi * 16 + gr;
                float h0 = 0.f, h1 = 0.f;
                if (j < HID) {
                    float br = bs[0][jl], bz = bs[1][jl], bin = bs[2][jl], bhn = bs[3][jl];
                    float r0 = 1.f / (1.f + expf(-(cc[0] + br)));
                    float z0 = 1.f / (1.f + expf(-(cc[1] + bz)));
                    float nn0 = tanhf(p0 + bin + r0 * (p1 + bhn));
                    h0 = (1.f - z0) * nn0 + z0 * OLD[jl * 128 + m0];
                    float r1 = 1.f / (1.f + expf(-(cc[2] + br)));
                    float z1 = 1.f / (1.f + expf(-(cc[3] + bz)));
                    float nn1 = tanhf(p2 + bin + r1 * (p3 + bhn));
                    h1 = (1.f - z1) * nn1 + z1 * OLD[jl * 128 + m0 + 8];
                }
                stF[jl * 132 + m0] = h0;
                stF[jl * 132 + m0 + 8] = h1;
            }
        }
    __syncthreads();

    // ---- coalesced writeout ----
    {   // new h fp32, [j][n]
        float *hTnew = g_hT + ((size_t)(bufo * 2 + dir) * 256 + jt * 32) * N_TOT + n0;
#pragma unroll
        for (int it = 0; it < 16; it++) {
            int idx = tid + it * 256;
            int jl = idx >> 7, nl = idx & 127;
            hTnew[(size_t)jl * N_TOT + nl] = stF[jl * 132 + nl];
        }
    }
    {   // tup fp32 [n][j], and h bf16 hi/lo [part][n][256]
        __nv_bfloat16 *hbo = g_hbf + (size_t)((bufo * 2 + dir) * 2) * N_TOT * 256;
        float *tupp = g_tup + (((size_t)dir * T_SEQ + t) * N_TOT) * HID;
#pragma unroll
        for (int it = 0; it < 2; it++) {
            int l = tid + it * 256;
            int nl = l >> 2, seg = l & 3;
            int n = n0 + nl;
            int jb = seg * 8;
            float v[8];
#pragma unroll
            for (int q = 0; q < 8; q++) v[q] = stF[(jb + q) * 132 + nl];
#pragma unroll
            for (int q = 0; q < 8; q++) {
                int j = jt * 32 + jb + q;
                if (j < HID) tupp[(size_t)n * HID + j] = v[q];
            }
            __nv_bfloat16 hi[8], lo[8];
#pragma unroll
            for (int q = 0; q < 8; q++) {
                hi[q] = __float2bfloat16(v[q]);
                lo[q] = __float2bfloat16(v[q] - __bfloat162float(hi[q]));
            }
            uint4 vh, vl;
            vh.x = pack2(hi[0], hi[1]); vh.y = pack2(hi[2], hi[3]);
            vh.z = pack2(hi[4], hi[5]); vh.w = pack2(hi[6], hi[7]);
            vl.x = pack2(lo[0], lo[1]); vl.y = pack2(lo[2], lo[3]);
            vl.z = pack2(lo[4], lo[5]); vl.w = pack2(lo[6], lo[7]);
            *(uint4 *)(hbo + (size_t)n * 256 + jt * 32 + jb) = vh;
            *(uint4 *)(hbo + (size_t)N_TOT * 256 + (size_t)n * 256 + jt * 32 + jb) = vl;
        }
    }
}

// ---------------- word-level attention ----------------
__global__ void __launch_bounds__(256) attn_kernel(const float *__restrict__ att_w) {
    const int n = blockIdx.x;
    const int tid = threadIdx.x;
    __shared__ float xsum[HID];
    __shared__ float red[8];
    __shared__ float s_bc;
    float acc = 0.f, m = -1e30f, denom = 0.f;
    float w = (tid < HID) ? att_w[tid] : 0.f;
    for (int t = 0; t < T_SEQ; t++) {
        if (tid < HID) {
            size_t i0 = (((size_t)0 * T_SEQ + t) * N_TOT + n) * HID + tid;
            size_t i1 = (((size_t)1 * T_SEQ + t) * N_TOT + n) * HID + tid;
            xsum[tid] = g_tup[i0] + g_tup[i1];
        }
        __syncthreads();
        float part = (tid < HID) ? tanhf(xsum[tid]) * w : 0.f;
#pragma unroll
        for (int o = 16; o > 0; o >>= 1) part += __shfl_down_sync(0xffffffffu, part, o);
        if ((tid & 31) == 0) red[tid >> 5] = part;
        __syncthreads();
        if (tid == 0) {
            float sm = 0.f;
#pragma unroll
            for (int q = 0; q < 8; q++) sm += red[q];
            s_bc = sm;
        }
        __syncthreads();
        float st = s_bc;
        float mn = fmaxf(m, st);
        float cc = expf(m - mn), e = expf(st - mn);
        denom = denom * cc + e;
        if (tid < HID) acc = acc * cc + e * xsum[tid];
        m = mn;
        __syncthreads();
    }
    if (tid < HID) g_repre[n * HID + tid] = tanhf(acc / denom);
}

// ---------------- bag attention ----------------
__global__ void __launch_bounds__(256) bag_kernel(const float *__restrict__ sen_a,
                                                  const float *__restrict__ sen_r) {
    const int b = blockIdx.x;
    const int tid = threadIdx.x;
    __shared__ float R[BAGSZ][HID];
    __shared__ float sv[BAGSZ];
    __shared__ float alpha[BAGSZ];
    for (int l = tid; l < BAGSZ * HID; l += 256) {
        int i = l / HID, j = l % HID;
        R[i][j] = g_repre[(b * BAGSZ + i) * HID + j];
    }
    __syncthreads();
    int wid = tid >> 5, lane = tid & 31;
    for (int i = wid; i < BAGSZ; i += 8) {
        float p = 0.f;
        for (int j = lane; j < HID; j += 32) p += R[i][j] * sen_a[j] * sen_r[j];
#pragma unroll
        for (int o = 16; o > 0; o >>= 1) p += __shfl_down_sync(0xffffffffu, p, o);
        if (lane == 0) sv[i] = p;
    }
    __syncthreads();
    if (tid == 0) {
        float mm = -1e30f;
        for (int i = 0; i < BAGSZ; i++) mm = fmaxf(mm, sv[i]);
        float ss = 0.f;
        for (int i = 0; i < BAGSZ; i++) { float e = expf(sv[i] - mm); alpha[i] = e; ss += e; }
        for (int i = 0; i < BAGSZ; i++) alpha[i] /= ss;
    }
    __syncthreads();
    for (int j = tid; j < HID; j += 256) {
        float a = 0.f;
#pragma unroll 4
        for (int i = 0; i < BAGSZ; i++) a += alpha[i] * R[i][j];
        g_sen_s[b * HID + j] = a;
    }
}

// ---------------- logits / prob / bce / acc ----------------
__global__ void __launch_bounds__(128) logits_kernel(const float *__restrict__ rel,
                                                     const float *__restrict__ sen_d,
                                                     const float *__restrict__ y,
                                                     float *__restrict__ out) {
    const int b = blockIdx.x;
    const int tid = threadIdx.x;
    __shared__ float ss[HID];
    __shared__ float lg[NREL];
    __shared__ float mmax;
    __shared__ int amax;
    __shared__ float dsum;
    for (int j = tid; j < HID; j += 128) ss[j] = g_sen_s[b * HID + j];
    __syncthreads();
    if (tid < NREL) {
        float a = sen_d[tid];
        const float *row = rel + (size_t)tid * HID;
        for (int j = 0; j < HID; j++) a += ss[j] * row[j];
        lg[tid] = a;
    }
    __syncthreads();
    if (tid == 0) {
        float mm = lg[0]; int am = 0;
        for (int c = 1; c < NREL; c++) if (lg[c] > mm) { mm = lg[c]; am = c; }
        mmax = mm; amax = am;
        float sum = 0.f;
        for (int c = 0; c < NREL; c++) sum += expf(lg[c] - mm);
        dsum = sum;
    }
    __syncthreads();
    if (tid < NREL) out[1 + NBAG + b * NREL + tid] = expf(lg[tid] - mmax) / dsum;
    if (tid == 0) {
        float loss = 0.f; int lab = 0;
        for (int c = 0; c < NREL; c++) {
            float l = lg[c], yv = y[b * NREL + c];
            loss += fmaxf(l, 0.f) - l * yv + log1pf(expf(-fabsf(l)));
            if (yv > 0.5f) lab = c;
        }
        g_loss_part[b] = loss / (float)NREL;
        out[1 + b] = (amax == lab) ? 1.f : 0.f;
    }
}

__global__ void loss_sum_kernel(float *__restrict__ out) {
    if (threadIdx.x == 0) {
        float s = 0.f;
        for (int b = 0; b < NBAG; b++) s += g_loss_part[b];
        out[0] = s;
    }
}

// ---------------- launch ----------------
extern "C" void kernel_launch(void *const *d_in, const int *in_sizes, int n_in,
                              void *d_out, int out_size) {
    const int *sentence = (const int *)d_in[0];
    const int *pos1 = (const int *)d_in[1];
    const int *pos2 = (const int *)d_in[2];
    const float *y_batch = (const float *)d_in[4];
    const float *word_emb = (const float *)d_in[5];
    const float *p1t = (const float *)d_in[6];
    const float *p2t = (const float *)d_in[7];
    const float *Wihf = (const float *)d_in[8];
    const float *Whhf = (const float *)d_in[9];
    const float *bihf = (const float *)d_in[10];
    const float *bhhf = (const float *)d_in[11];
    const float *Wihb = (const float *)d_in[12];
    const float *Whhb = (const float *)d_in[13];
    const float *bihb = (const float *)d_in[14];
    const float *bhhb = (const float *)d_in[15];
    const float *attw = (const float *)d_in[16];
    const float *sena = (const float *)d_in[17];
    const float *senr = (const float *)d_in[18];
    const float *rel = (const float *)d_in[19];
    const float *send = (const float *)d_in[20];
    float *out = (float *)d_out;

    cudaFuncSetAttribute(gru_step_kernel, cudaFuncAttributeMaxDynamicSharedMemorySize, SMEM_DYN);

    zero_kernel<<<(int)(((size_t)2 * 2 * 256 * N_TOT + 255) / 256), 256>>>();
    prep_w_kernel<<<(2 * 8 * 10 * 128 * 32 + 255) / 256, 256>>>(Wihf, Whhf, Wihb, Whhb);
    gather_kernel<<<(int)(((size_t)N_TOT * T_SEQ * 64 + 255) / 256), 256>>>(
        sentence, pos1, pos2, word_emb, p1t, p2t);

    dim3 grid(16, 8, 2);
    for (int s = 0; s < T_SEQ; s++) {
        gru_step_kernel<<<grid, 256, SMEM_DYN>>>(s, bihf, bhhf, bihb, bhhb);
    }

    attn_kernel<<<N_TOT, 256>>>(attw);
    bag_kernel<<<NBAG, 256>>>(sena, senr);
    logits_kernel<<<NBAG, 128>>>(rel, send, y_batch, out);
    loss_sum_kernel<<<1, 32>>>(out);
}

// round 5
// speedup vs baseline: 1.4749x; 1.0792x over previous
#include <cuda_runtime.h>
#include <cuda_bf16.h>
#include <math.h>
#include <stdint.h>

#define N_TOT 2048
#define T_SEQ 70
#define HID   230
#define DIN   60
#define EMB_W 50
#define NBAG  64
#define BAGSZ 32
#define NREL  100

// GRU step: M=128, N=96 (32j x 3 gates), K=320 (2 emb chunks + 8 h chunks of 32)
// stage: A_hi[128*64B] A_lo B_hi[96*64B] B_lo, XOR-swizzled 64B rows
#define STAGE_B  28672
#define A_LO_OFF 8192
#define B_HI_OFF 16384
#define B_LO_OFF 22528
#define DUMP_OFF (3 * STAGE_B)            // 86016
#define SMEM_DYN (DUMP_OFF + 32 * 132 * 4) // 102912

// ---------------- device scratch ----------------
__device__ __align__(128) __nv_bfloat16 g_Wt[(size_t)2 * 8 * 2 * 10 * 96 * 32]; // [dir][jt][part][chunk][96][32]
__device__ __align__(128) __nv_bfloat16 g_embsp[(size_t)T_SEQ * 2 * N_TOT * 64]; // [t][part][n][64]
__device__ __align__(128) __nv_bfloat16 g_hbf[(size_t)2 * 2 * 2 * N_TOT * 256];  // [buf][dir][part][n][256]
__device__ float g_hT[(size_t)2 * 2 * 256 * N_TOT];                               // [buf][dir][j][n]
__device__ float g_tup[(size_t)2 * T_SEQ * N_TOT * HID];                          // [dir][t][n][j]
__device__ float g_repre[N_TOT * HID];
__device__ float g_sen_s[NBAG * HID];
__device__ float g_loss_part[NBAG];

// ---------------- ptx helpers ----------------
__device__ __forceinline__ uint32_t smem_u32(const void *p) {
    uint32_t a;
    asm("{ .reg .u64 t; cvta.to.shared.u64 t, %1; cvt.u32.u64 %0, t; }" : "=r"(a) : "l"(p));
    return a;
}
__device__ __forceinline__ void cpa16(uint32_t dst, const void *src) {
    asm volatile("cp.async.ca.shared.global [%0], [%1], 16;" :: "r"(dst), "l"(src));
}
#define CP_COMMIT() asm volatile("cp.async.commit_group;" ::: "memory")
#define CP_WAIT1()  asm volatile("cp.async.wait_group 1;" ::: "memory")
#define CP_WAIT0()  asm volatile("cp.async.wait_group 0;" ::: "memory")
#define LDSM4(r, a)                                                                   \
    asm volatile("ldmatrix.sync.aligned.m8n8.x4.shared.b16 {%0,%1,%2,%3}, [%4];"      \
                 : "=r"((r)[0]), "=r"((r)[1]), "=r"((r)[2]), "=r"((r)[3]) : "r"(a))
#define MMA16816(c, a, b0, b1)                                                        \
    asm volatile("mma.sync.aligned.m16n8k16.row.col.f32.bf16.bf16.f32 "               \
                 "{%0,%1,%2,%3},{%4,%5,%6,%7},{%8,%9},{%0,%1,%2,%3};"                 \
                 : "+f"((c)[0]), "+f"((c)[1]), "+f"((c)[2]), "+f"((c)[3])             \
                 : "r"((a)[0]), "r"((a)[1]), "r"((a)[2]), "r"((a)[3]), "r"(b0), "r"(b1))

__device__ __forceinline__ uint32_t pack2(__nv_bfloat16 a, __nv_bfloat16 b) {
    unsigned short ra = *(unsigned short *)&a, rb = *(unsigned short *)&b;
    return (uint32_t)ra | ((uint32_t)rb << 16);
}
// swizzled byte offset within a 64B-row array
__device__ __forceinline__ uint32_t swz(int row, int seg) {
    return (uint32_t)row * 64u + (uint32_t)((seg ^ ((row >> 1) & 3)) << 4);
}

// ---------------- prep kernels ----------------
__global__ void zero_kernel() {
    size_t i = (size_t)blockIdx.x * blockDim.x + threadIdx.x;
    size_t nh = (size_t)2 * 2 * 2 * N_TOT * 256 / 2;
    if (i < nh) ((uint32_t *)g_hbf)[i] = 0u;
    if (i < (size_t)2 * 2 * 256 * N_TOT) g_hT[i] = 0.f;
}

// weights -> [dir][jt][part][chunk(10)][row 96][k 32], row = j_local*3 + gate
// chunks 0-1: Wih (k=c*32+kc within 60), chunks 2-9: Whh (kh=(c-2)*32+kc within 230)
__global__ void prep_w_kernel(const float *__restrict__ Wihf, const float *__restrict__ Whhf,
                              const float *__restrict__ Wihb, const float *__restrict__ Whhb) {
    int idx = blockIdx.x * blockDim.x + threadIdx.x;
    if (idx >= 2 * 8 * 10 * 96 * 32) return;
    int kc = idx & 31;
    int r = (idx >> 5) % 96;
    int rest = idx / (96 * 32);      // 0..159
    int c = rest % 10;
    int jt = (rest / 10) & 7;
    int dir = rest / 80;
    const float *Wih = dir ? Wihb : Wihf;
    const float *Whh = dir ? Whhb : Whhf;
    int j = jt * 32 + r / 3;
    int g = r % 3;
    float v = 0.f;
    if (j < HID) {
        if (c < 2) {
            int k = c * 32 + kc;
            if (k < DIN) v = Wih[(g * HID + j) * DIN + k];
        } else {
            int kh = (c - 2) * 32 + kc;
            if (kh < HID) v = Whh[(g * HID + j) * HID + kh];
        }
    }
    __nv_bfloat16 hi = __float2bfloat16(v);
    __nv_bfloat16 lo = __float2bfloat16(v - __bfloat162float(hi));
    size_t i0 = ((((size_t)(dir * 8 + jt) * 2 + 0) * 10 + c) * 96 + r) * 32 + kc;
    size_t i1 = ((((size_t)(dir * 8 + jt) * 2 + 1) * 10 + c) * 96 + r) * 32 + kc;
    g_Wt[i0] = hi;
    g_Wt[i1] = lo;
}

__global__ void gather_kernel(const int *__restrict__ sent, const int *__restrict__ p1,
                              const int *__restrict__ p2, const float *__restrict__ wemb,
                              const float *__restrict__ p1t, const float *__restrict__ p2t) {
    size_t idx = (size_t)blockIdx.x * blockDim.x + threadIdx.x;
    if (idx >= (size_t)N_TOT * T_SEQ * 64) return;
    int k = (int)(idx & 63);
    size_t nt = idx >> 6;
    int t = (int)(nt % T_SEQ);
    int n = (int)(nt / T_SEQ);
    float v = 0.f;
    if (k < EMB_W) v = wemb[(size_t)sent[n * T_SEQ + t] * EMB_W + k];
    else if (k < EMB_W + 5) v = p1t[p1[n * T_SEQ + t] * 5 + (k - EMB_W)];
    else if (k < DIN) v = p2t[p2[n * T_SEQ + t] * 5 + (k - EMB_W - 5)];
    __nv_bfloat16 hi = __float2bfloat16(v);
    __nv_bfloat16 lo = __float2bfloat16(v - __bfloat162float(hi));
    g_embsp[((size_t)(t * 2 + 0) * N_TOT + n) * 64 + k] = hi;
    g_embsp[((size_t)(t * 2 + 1) * N_TOT + n) * 64 + k] = lo;
}

// ---------------- GRU step (mma.sync bf16, 3-pass split, 3-stage pipeline) --
__global__ void __launch_bounds__(256, 2) gru_step_kernel(
    int s,
    const float *__restrict__ bihf, const float *__restrict__ bhhf,
    const float *__restrict__ bihb, const float *__restrict__ bhhb) {
    extern __shared__ char dsm[];
    const int dir = blockIdx.z;
    const int t = dir ? (T_SEQ - 1 - s) : s;
    const int n0 = blockIdx.x * 128;
    const int jt = blockIdx.y;
    const int tid = threadIdx.x;
    const int lane = tid & 31, wid = tid >> 5;
    const int warpM = wid & 3, warpN = wid >> 2;
    const int bufi = s & 1, bufo = (s + 1) & 1;
    const float *bih = dir ? bihb : bihf;
    const float *bhh = dir ? bhhb : bhhf;

    const uint32_t base = smem_u32(dsm);
    float *dumpIN = (float *)(dsm + DUMP_OFF);
    __shared__ float bs[4][32];
    if (tid < 32) {
        int j = jt * 32 + tid;
        bool ok = j < HID;
        bs[0][tid] = ok ? (bih[j] + bhh[j]) : 0.f;
        bs[1][tid] = ok ? (bih[HID + j] + bhh[HID + j]) : 0.f;
        bs[2][tid] = ok ? bih[2 * HID + j] : 0.f;
        bs[3][tid] = ok ? bhh[2 * HID + j] : 0.f;
    }

    const __nv_bfloat16 *embp = g_embsp + (size_t)t * 2 * N_TOT * 64 + (size_t)n0 * 64;
    const __nv_bfloat16 *hbfp = g_hbf + (size_t)((bufi * 2 + dir) * 2) * N_TOT * 256 + (size_t)n0 * 256;
    const __nv_bfloat16 *wbase = g_Wt + (size_t)(dir * 8 + jt) * 2 * 10 * (96 * 32);

    auto issue = [&](int c) {
        uint32_t st = base + (uint32_t)(c % 3) * STAGE_B;
#pragma unroll
        for (int part = 0; part < 2; part++) {
            const __nv_bfloat16 *Ap;
            int strideA;
            if (c < 2) { Ap = embp + (size_t)part * N_TOT * 64 + c * 32; strideA = 64; }
            else { Ap = hbfp + (size_t)part * N_TOT * 256 + (c - 2) * 32; strideA = 256; }
            // A: 128 rows x 4 segs
#pragma unroll
            for (int it = 0; it < 2; it++) {
                int l = it * 256 + tid;
                int row = l >> 2, seg = l & 3;
                cpa16(st + part * A_LO_OFF + swz(row, seg), Ap + (size_t)row * strideA + seg * 8);
            }
            // B: 96 rows x 4 segs = 384 items
            const __nv_bfloat16 *Bp = wbase + (size_t)(part * 10 + c) * (96 * 32);
            {
                int row = tid >> 2, seg = tid & 3;
                cpa16(st + B_HI_OFF + part * 6144 + swz(row, seg), Bp + row * 32 + seg * 8);
                int l = 256 + tid;
                if (l < 384) {
                    row = l >> 2; seg = l & 3;
                    cpa16(st + B_HI_OFF + part * 6144 + swz(row, seg), Bp + row * 32 + seg * 8);
                }
            }
        }
        CP_COMMIT();
    };

    issue(0);
    issue(1);

    float acc[2][6][4];
#pragma unroll
    for (int mi = 0; mi < 2; mi++)
#pragma unroll
        for (int ni = 0; ni < 6; ni++)
#pragma unroll
            for (int q = 0; q < 4; q++) acc[mi][ni][q] = 0.f;

    const int laneR = lane & 15;
    const int laneHi = lane >> 4;       // 16B group select
    const int gr = lane >> 2, lc = lane & 3;

    for (int c = 0; c < 10; c++) {
        if (c < 9) CP_WAIT1(); else CP_WAIT0();
        __syncthreads();
        if (c + 2 < 10) issue(c + 2);   // writes stage (c-1)%3; all warps done with it (sync)
        uint32_t sA = base + (uint32_t)(c % 3) * STAGE_B;
        uint32_t sB = sA + B_HI_OFF;
#pragma unroll
        for (int ks = 0; ks < 2; ks++) {
            uint32_t ah[2][4], al[2][4];
#pragma unroll
            for (int mi = 0; mi < 2; mi++) {
                int row = warpM * 32 + mi * 16 + laneR;
                uint32_t off = swz(row, ks * 2 + laneHi);
                LDSM4(ah[mi], sA + off);
                LDSM4(al[mi], sA + A_LO_OFF + off);
            }
#pragma unroll
            for (int np = 0; np < 3; np++) {
                int row = warpN * 48 + np * 16 + laneR;
                uint32_t off = swz(row, ks * 2 + laneHi);
                uint32_t bh[4], bl[4];
                LDSM4(bh, sB + off);
                LDSM4(bl, sB + 6144 + off);
#pragma unroll
                for (int mi = 0; mi < 2; mi++) {
                    float *c0 = acc[mi][np * 2];
                    float *c1 = acc[mi][np * 2 + 1];
                    MMA16816(c0, ah[mi], bh[0], bh[2]);
                    MMA16816(c0, ah[mi], bl[0], bl[2]);
                    MMA16816(c0, al[mi], bh[0], bh[2]);
                    MMA16816(c1, ah[mi], bh[1], bh[3]);
                    MMA16816(c1, ah[mi], bl[1], bl[3]);
                    MMA16816(c1, al[mi], bh[1], bh[3]);
                }
            }
        }
        if (c == 1) {
            // emb phase done: move i_n slots (col%3==2) to dumpIN, zero them
#pragma unroll
            for (int mi = 0; mi < 2; mi++)
#pragma unroll
                for (int ni = 0; ni < 6; ni++)
#pragma unroll
                    for (int b = 0; b < 2; b++) {
                        int col = warpN * 48 + ni * 8 + lc * 2 + b;
                        if (col % 3 == 2) {
                            int jl = col / 3;
                            int m0 = warpM * 32 + mi * 16 + gr;
                            dumpIN[jl * 132 + m0] = acc[mi][ni][b];
                            dumpIN[jl * 132 + m0 + 8] = acc[mi][ni][b + 2];
                            acc[mi][ni][b] = 0.f;
                            acc[mi][ni][b + 2] = 0.f;
                        }
                    }
        }
    }

    __syncthreads();   // all warps done reading stages; reuse for D staging
    float *D2 = (float *)dsm;   // [96 col][132]
#pragma unroll
    for (int mi = 0; mi < 2; mi++)
#pragma unroll
        for (int ni = 0; ni < 6; ni++) {
            int col0 = warpN * 48 + ni * 8 + lc * 2;
            int m0 = warpM * 32 + mi * 16 + gr;
            D2[col0 * 132 + m0] = acc[mi][ni][0];
            D2[(col0 + 1) * 132 + m0] = acc[mi][ni][1];
            D2[col0 * 132 + m0 + 8] = acc[mi][ni][2];
            D2[(col0 + 1) * 132 + m0 + 8] = acc[mi][ni][3];
        }
    __syncthreads();

    // gates: thread -> (jl, 16 n)
    {
        int jl = tid >> 3, nseg = tid & 7;
        int j = jt * 32 + jl;
        int nb = nseg * 16;
        float br = bs[0][jl], bz = bs[1][jl], bin = bs[2][jl], bhn = bs[3][jl];
        const float *holdp = g_hT + ((size_t)(bufi * 2 + dir) * 256 + j) * N_TOT + n0 + nb;
        float *hnewp = g_hT + ((size_t)(bufo * 2 + dir) * 256 + j) * N_TOT + n0 + nb;
        const float *Dr = D2 + (jl * 3 + 0) * 132 + nb;
        const float *Dz = D2 + (jl * 3 + 1) * 132 + nb;
        const float *Dn = D2 + (jl * 3 + 2) * 132 + nb;
        const float *Di = dumpIN + jl * 132 + nb;
        float hv[16];
#pragma unroll
        for (int i = 0; i < 16; i++) {
            float r = 1.f / (1.f + expf(-(Dr[i] + br)));
            float z = 1.f / (1.f + expf(-(Dz[i] + bz)));
            float nn = tanhf(Di[i] + bin + r * (Dn[i] + bhn));
            float h = (1.f - z) * nn + z * holdp[i];
            hv[i] = h;
            hnewp[i] = h;
        }
#pragma unroll
        for (int i = 0; i < 16; i++) ((float *)D2)[(jl * 3) * 132 + nb + i] = hv[i];
    }
    __syncthreads();

    // transposed writeout: tup fp32 [n][j], hbf hi/lo [part][n][256]
    {
        __nv_bfloat16 *hbo = g_hbf + (size_t)((bufo * 2 + dir) * 2) * N_TOT * 256;
        float *tupp = g_tup + (((size_t)dir * T_SEQ + t) * N_TOT) * HID;
#pragma unroll
        for (int it = 0; it < 2; it++) {
            int l = tid + it * 256;
            int nl = l >> 2, seg = l & 3;
            int n = n0 + nl;
            int jb = seg * 8;
            float v[8];
#pragma unroll
            for (int q = 0; q < 8; q++) v[q] = D2[((jb + q) * 3) * 132 + nl];
#pragma unroll
            for (int q = 0; q < 8; q++) {
                int j = jt * 32 + jb + q;
                if (j < HID) tupp[(size_t)n * HID + j] = v[q];
            }
            __nv_bfloat16 hi[8], lo[8];
#pragma unroll
            for (int q = 0; q < 8; q++) {
                hi[q] = __float2bfloat16(v[q]);
                lo[q] = __float2bfloat16(v[q] - __bfloat162float(hi[q]));
            }
            uint4 vh, vl;
            vh.x = pack2(hi[0], hi[1]); vh.y = pack2(hi[2], hi[3]);
            vh.z = pack2(hi[4], hi[5]); vh.w = pack2(hi[6], hi[7]);
            vl.x = pack2(lo[0], lo[1]); vl.y = pack2(lo[2], lo[3]);
            vl.z = pack2(lo[4], lo[5]); vl.w = pack2(lo[6], lo[7]);
            *(uint4 *)(hbo + (size_t)n * 256 + jt * 32 + jb) = vh;
            *(uint4 *)(hbo + (size_t)N_TOT * 256 + (size_t)n * 256 + jt * 32 + jb) = vl;
        }
    }
}

// ---------------- word-level attention ----------------
__global__ void __launch_bounds__(256) attn_kernel(const float *__restrict__ att_w) {
    const int n = blockIdx.x;
    const int tid = threadIdx.x;
    __shared__ float xsum[HID];
    __shared__ float red[8];
    __shared__ float s_bc;
    float acc = 0.f, m = -1e30f, denom = 0.f;
    float w = (tid < HID) ? att_w[tid] : 0.f;
    for (int t = 0; t < T_SEQ; t++) {
        if (tid < HID) {
            size_t i0 = (((size_t)0 * T_SEQ + t) * N_TOT + n) * HID + tid;
            size_t i1 = (((size_t)1 * T_SEQ + t) * N_TOT + n) * HID + tid;
            xsum[tid] = g_tup[i0] + g_tup[i1];
        }
        __syncthreads();
        float part = (tid < HID) ? tanhf(xsum[tid]) * w : 0.f;
#pragma unroll
        for (int o = 16; o > 0; o >>= 1) part += __shfl_down_sync(0xffffffffu, part, o);
        if ((tid & 31) == 0) red[tid >> 5] = part;
        __syncthreads();
        if (tid == 0) {
            float sm = 0.f;
#pragma unroll
            for (int q = 0; q < 8; q++) sm += red[q];
            s_bc = sm;
        }
        __syncthreads();
        float st = s_bc;
        float mn = fmaxf(m, st);
        float cc = expf(m - mn), e = expf(st - mn);
        denom = denom * cc + e;
        if (tid < HID) acc = acc * cc + e * xsum[tid];
        m = mn;
        __syncthreads();
    }
    if (tid < HID) g_repre[n * HID + tid] = tanhf(acc / denom);
}

// ---------------- bag attention ----------------
__global__ void __launch_bounds__(256) bag_kernel(const float *__restrict__ sen_a,
                                                  const float *__restrict__ sen_r) {
    const int b = blockIdx.x;
    const int tid = threadIdx.x;
    __shared__ float R[BAGSZ][HID];
    __shared__ float sv[BAGSZ];
    __shared__ float alpha[BAGSZ];
    for (int l = tid; l < BAGSZ * HID; l += 256) {
        int i = l / HID, j = l % HID;
        R[i][j] = g_repre[(b * BAGSZ + i) * HID + j];
    }
    __syncthreads();
    int wid = tid >> 5, lane = tid & 31;
    for (int i = wid; i < BAGSZ; i += 8) {
        float p = 0.f;
        for (int j = lane; j < HID; j += 32) p += R[i][j] * sen_a[j] * sen_r[j];
#pragma unroll
        for (int o = 16; o > 0; o >>= 1) p += __shfl_down_sync(0xffffffffu, p, o);
        if (lane == 0) sv[i] = p;
    }
    __syncthreads();
    if (tid == 0) {
        float mm = -1e30f;
        for (int i = 0; i < BAGSZ; i++) mm = fmaxf(mm, sv[i]);
        float ss = 0.f;
        for (int i = 0; i < BAGSZ; i++) { float e = expf(sv[i] - mm); alpha[i] = e; ss += e; }
        for (int i = 0; i < BAGSZ; i++) alpha[i] /= ss;
    }
    __syncthreads();
    for (int j = tid; j < HID; j += 256) {
        float a = 0.f;
#pragma unroll 4
        for (int i = 0; i < BAGSZ; i++) a += alpha[i] * R[i][j];
        g_sen_s[b * HID + j] = a;
    }
}

// ---------------- logits / prob / bce / acc ----------------
__global__ void __launch_bounds__(128) logits_kernel(const float *__restrict__ rel,
                                                     const float *__restrict__ sen_d,
                                                     const float *__restrict__ y,
                                                     float *__restrict__ out) {
    const int b = blockIdx.x;
    const int tid = threadIdx.x;
    __shared__ float ss[HID];
    __shared__ float lg[NREL];
    __shared__ float mmax;
    __shared__ int amax;
    __shared__ float dsum;
    for (int j = tid; j < HID; j += 128) ss[j] = g_sen_s[b * HID + j];
    __syncthreads();
    if (tid < NREL) {
        float a = sen_d[tid];
        const float *row = rel + (size_t)tid * HID;
        for (int j = 0; j < HID; j++) a += ss[j] * row[j];
        lg[tid] = a;
    }
    __syncthreads();
    if (tid == 0) {
        float mm = lg[0]; int am = 0;
        for (int c = 1; c < NREL; c++) if (lg[c] > mm) { mm = lg[c]; am = c; }
        mmax = mm; amax = am;
        float sum = 0.f;
        for (int c = 0; c < NREL; c++) sum += expf(lg[c] - mm);
        dsum = sum;
    }
    __syncthreads();
    if (tid < NREL) out[1 + NBAG + b * NREL + tid] = expf(lg[tid] - mmax) / dsum;
    if (tid == 0) {
        float loss = 0.f; int lab = 0;
        for (int c = 0; c < NREL; c++) {
            float l = lg[c], yv = y[b * NREL + c];
            loss += fmaxf(l, 0.f) - l * yv + log1pf(expf(-fabsf(l)));
            if (yv > 0.5f) lab = c;
        }
        g_loss_part[b] = loss / (float)NREL;
        out[1 + b] = (amax == lab) ? 1.f : 0.f;
    }
}

__global__ void loss_sum_kernel(float *__restrict__ out) {
    if (threadIdx.x == 0) {
        float s = 0.f;
        for (int b = 0; b < NBAG; b++) s += g_loss_part[b];
        out[0] = s;
    }
}

// ---------------- launch ----------------
extern "C" void kernel_launch(void *const *d_in, const int *in_sizes, int n_in,
                              void *d_out, int out_size) {
    const int *sentence = (const int *)d_in[0];
    const int *pos1 = (const int *)d_in[1];
    const int *pos2 = (const int *)d_in[2];
    const float *y_batch = (const float *)d_in[4];
    const float *word_emb = (const float *)d_in[5];
    const float *p1t = (const float *)d_in[6];
    const float *p2t = (const float *)d_in[7];
    const float *Wihf = (const float *)d_in[8];
    const float *Whhf = (const float *)d_in[9];
    const float *bihf = (const float *)d_in[10];
    const float *bhhf = (const float *)d_in[11];
    const float *Wihb = (const float *)d_in[12];
    const float *Whhb = (const float *)d_in[13];
    const float *bihb = (const float *)d_in[14];
    const float *bhhb = (const float *)d_in[15];
    const float *attw = (const float *)d_in[16];
    const float *sena = (const float *)d_in[17];
    const float *senr = (const float *)d_in[18];
    const float *rel = (const float *)d_in[19];
    const float *send = (const float *)d_in[20];
    float *out = (float *)d_out;

    cudaFuncSetAttribute(gru_step_kernel, cudaFuncAttributeMaxDynamicSharedMemorySize, SMEM_DYN);

    zero_kernel<<<(int)(((size_t)2 * 2 * 256 * N_TOT + 255) / 256), 256>>>();
    prep_w_kernel<<<(2 * 8 * 10 * 96 * 32 + 255) / 256, 256>>>(Wihf, Whhf, Wihb, Whhb);
    gather_kernel<<<(int)(((size_t)N_TOT * T_SEQ * 64 + 255) / 256), 256>>>(
        sentence, pos1, pos2, word_emb, p1t, p2t);

    dim3 grid(16, 8, 2);
    for (int s = 0; s < T_SEQ; s++) {
        gru_step_kernel<<<grid, 256, SMEM_DYN>>>(s, bihf, bhhf, bihb, bhhb);
    }

    attn_kernel<<<N_TOT, 256>>>(attw);
    bag_kernel<<<NBAG, 256>>>(sena, senr);
    logits_kernel<<<NBAG, 128>>>(rel, send, y_batch, out);
    loss_sum_kernel<<<1, 32>>>(out);
}